// round 14
// baseline (speedup 1.0000x reference)
#include <cuda_runtime.h>
#include <cuda_fp16.h>
#include <cstdint>
#include <math.h>

#define T_TOK 1024
#define HDIM  1024
#define NEXP  16
#define TOPK  4
#define NPAIR (T_TOK*TOPK)

__device__ __half g_tnormh[T_TOK*HDIM];
__device__ __half g_acth[NPAIR*HDIM];
__device__ __half g_yh[NPAIR*HDIM];
__device__ float  g_wgt[NPAIR];
__device__ int    g_plist[NEXP*T_TOK];
__device__ int    g_cnt[NEXP];          // zero-init at load; re-zeroed by k_combine

// ---------------- helpers ----------------
__device__ __forceinline__ uint32_t smem_u32(const void* p) {
    uint32_t a;
    asm("{ .reg .u64 t; cvta.to.shared.u64 t, %1; cvt.u32.u64 %0, t; }" : "=r"(a) : "l"(p));
    return a;
}
__device__ __forceinline__ void cp16(uint32_t dst, const void* src, int srcbytes) {
    asm volatile("cp.async.cg.shared.global [%0], [%1], 16, %2;"
                 :: "r"(dst), "l"(src), "r"(srcbytes) : "memory");
}
__device__ __forceinline__ void cp_commit() {
    asm volatile("cp.async.commit_group;" ::: "memory");
}
template<int N> __device__ __forceinline__ void cp_wait() {
    asm volatile("cp.async.wait_group %0;" :: "n"(N) : "memory");
}
__device__ __forceinline__ uint32_t packh2(float lo, float hi) {
    uint32_t r;
    asm("cvt.rn.f16x2.f32 %0, %1, %2;" : "=r"(r) : "f"(hi), "f"(lo));
    return r;
}
__device__ __forceinline__ void ldsm4(uint32_t* r, uint32_t a) {
    asm volatile("ldmatrix.sync.aligned.m8n8.x4.shared.b16 {%0,%1,%2,%3}, [%4];"
                 : "=r"(r[0]), "=r"(r[1]), "=r"(r[2]), "=r"(r[3]) : "r"(a));
}
__device__ __forceinline__ void mma16816(float* d, const uint32_t* a, const uint32_t* b) {
    asm volatile("mma.sync.aligned.m16n8k16.row.col.f32.f16.f16.f32 "
                 "{%0,%1,%2,%3}, {%4,%5,%6,%7}, {%8,%9}, {%0,%1,%2,%3};"
                 : "+f"(d[0]), "+f"(d[1]), "+f"(d[2]), "+f"(d[3])
                 : "r"(a[0]), "r"(a[1]), "r"(a[2]), "r"(a[3]), "r"(b[0]), "r"(b[1]));
}

// ---------------- RMSNorm + router + top-4 + dispatch ----------------
__global__ void k_norm_router(const float* __restrict__ x, const float* __restrict__ nw,
                              const float* __restrict__ rw, const float* __restrict__ rb,
                              const float* __restrict__ mw, const int* __restrict__ lip)
{
    const int t = blockIdx.x, tid = threadIdx.x;
    const int wid = tid >> 5, lane = tid & 31;

    float4 xv = ((const float4*)(x + (size_t)t * HDIM))[tid];
    float ss = xv.x*xv.x + xv.y*xv.y + xv.z*xv.z + xv.w*xv.w;

    __shared__ float sw8[8];
    #pragma unroll
    for (int o = 16; o; o >>= 1) ss += __shfl_xor_sync(~0u, ss, o);
    if (lane == 0) sw8[wid] = ss;
    __syncthreads();
    __shared__ float s_scale;
    if (tid == 0) {
        float tot = 0.f;
        #pragma unroll
        for (int i = 0; i < 8; i++) tot += sw8[i];
        s_scale = rsqrtf(tot / (float)HDIM + 1e-5f);
    }
    __syncthreads();
    const float s = s_scale;

    float4 nv = ((const float4*)nw)[tid];
    float4 tv = make_float4(xv.x*s*nv.x, xv.y*s*nv.y, xv.z*s*nv.z, xv.w*s*nv.w);
    {
        __half2* th = (__half2*)(g_tnormh + (size_t)t * HDIM);
        th[tid*2]   = __floats2half2_rn(tv.x, tv.y);
        th[tid*2+1] = __floats2half2_rn(tv.z, tv.w);
    }

    float p[NEXP];
    #pragma unroll
    for (int e = 0; e < NEXP; e++) {
        float4 wv = ((const float4*)(rw + (size_t)e * HDIM))[tid];
        p[e] = tv.x*wv.x + tv.y*wv.y + tv.z*wv.z + tv.w*wv.w;
    }
    __shared__ float sall[8][NEXP];
    #pragma unroll
    for (int e = 0; e < NEXP; e++) {
        float v = p[e];
        #pragma unroll
        for (int o = 16; o; o >>= 1) v += __shfl_xor_sync(~0u, v, o);
        if (lane == 0) sall[wid][e] = v;
    }
    __syncthreads();

    if (tid == 0) {
        float g[NEXP];
        #pragma unroll
        for (int e = 0; e < NEXP; e++) {
            float v = 0.f;
            #pragma unroll
            for (int w = 0; w < 8; w++) v += sall[w][e];
            g[e] = v + rb[e];
        }
        const int li = lip ? lip[0] : 0;
        float ma = 0.f;
        #pragma unroll
        for (int e = 0; e < NEXP; e++) ma = fmaxf(ma, fabsf(mw[li*NEXP + e]));
        if (ma > 0.f) {
            float m = -1e30f;
            for (int e = 0; e < NEXP; e++) m = fmaxf(m, g[e]);
            float se = 0.f;
            for (int e = 0; e < NEXP; e++) se += expf(g[e] - m);
            const float lse = m + logf(se);
            float gl[NEXP], mx = -1e30f, mn = 1e30f;
            for (int e = 0; e < NEXP; e++) {
                gl[e] = g[e] - lse;
                mx = fmaxf(mx, gl[e]); mn = fminf(mn, gl[e]);
            }
            for (int e = 0; e < NEXP; e++) {
                const float l = mw[li*NEXP + e];
                g[e] = (l > 0.f) ? mx + 0.01f : (l < 0.f) ? mn - 0.01f : gl[e];
            }
        }
        int idx[TOPK]; float val[TOPK]; unsigned used = 0;
        #pragma unroll
        for (int k = 0; k < TOPK; k++) {
            int b = 0; float bv = -1e38f;
            for (int e = 0; e < NEXP; e++)
                if (!((used >> e) & 1u) && g[e] > bv) { bv = g[e]; b = e; }
            used |= 1u << b; idx[k] = b; val[k] = bv;
        }
        const float m0 = val[0];
        float wsum = 0.f, wv2[TOPK];
        #pragma unroll
        for (int k = 0; k < TOPK; k++) { wv2[k] = expf(val[k] - m0); wsum += wv2[k]; }
        #pragma unroll
        for (int k = 0; k < TOPK; k++) {
            const int e = idx[k];
            const int pos = atomicAdd(&g_cnt[e], 1);
            g_plist[e * T_TOK + pos] = t * TOPK + k;
            g_wgt[t * TOPK + k] = wv2[k] / wsum;
        }
    }
}

// ---------------- fp16 mma GEMM (R12 structure + m-tile validity skip) -----
#define NSTG  6
#define ASTRH 24
#define ABYT  (128*ASTRH*2)
#define BSTR  132
#define BBYT  (16*BSTR*4)
#define OFF_B (NSTG*ABYT)
#define SMEM_MMA (NSTG*(ABYT + BBYT))   // 87552 B

template<int IS_G1>
__global__ __launch_bounds__(256, 2)
void k_mma(const float* __restrict__ W, const float* __restrict__ bias)
{
    const int e = blockIdx.z;
    const int n = g_cnt[e];
    const int row0 = blockIdx.y * 128;
    if (row0 >= n) return;

    extern __shared__ char dsm[];
    __shared__ float sbias[128];
    __shared__ int   spid[128];
    __shared__ float swgt[128];

    const int tid = threadIdx.x, lane = tid & 31, wid = tid >> 5;
    const int g = lane >> 2, tg = lane & 3;
    const int warp_m = wid >> 2, warp_n = wid & 3;
    const int c0 = blockIdx.x * (IS_G1 ? 64 : 128);

    if (tid < 128) {
        const int r = row0 + tid;
        const int p = (r < n) ? g_plist[e * T_TOK + r] : -1;
        spid[tid] = p;
        if (!IS_G1) swgt[tid] = (p >= 0) ? g_wgt[p] : 0.f;
        if (IS_G1)
            sbias[tid] = (tid < 64) ? bias[e*2048 + c0 + tid]
                                    : bias[e*2048 + 1024 + c0 + (tid - 64)];
        else
            sbias[tid] = bias[e*1024 + c0 + tid];
    }
    __syncthreads();

    const __half* Aglob = IS_G1 ? g_tnormh : g_acth;
    const int arow = tid >> 1;
    const int akc  = (tid & 1) * 8;
    const int apid = spid[arow];
    const long aoff = (apid < 0) ? 0 : (IS_G1 ? (long)(apid >> 2) * HDIM : (long)apid * HDIM);
    const int avalid = (apid >= 0) ? 16 : 0;

    const int bk  = tid >> 4;
    const int bcl = (tid & 15) * 8;
    const long bstride = IS_G1 ? 2048 : 1024;
    const float* Wg = W + (size_t)e * (size_t)bstride * 1024;
    long bcol;
    if (IS_G1) bcol = (bcl < 64) ? (long)(c0 + bcl) : (long)(1024 + c0 + (bcl - 64));
    else       bcol = (long)(c0 + bcl);

    const uint32_t sBase = smem_u32(dsm);
    const uint32_t aDst = sBase + (uint32_t)(arow * ASTRH + akc) * 2;
    const uint32_t bDst = sBase + OFF_B + (uint32_t)(bk * BSTR + bcl) * 4;

    const int a_rin = ((lane >> 3) & 1) * 8 + (lane & 7);
    const uint32_t aFrag = sBase + (uint32_t)((warp_m*64 + a_rin) * ASTRH) * 2
                         + (uint32_t)(lane >> 4) * 16;

    // ---- m-tile validity: skip MMA work for fully-invalid 16-row tiles ----
    bool mv[4];
    #pragma unroll
    for (int mt = 0; mt < 4; mt++)
        mv[mt] = (row0 + warp_m*64 + mt*16) < n;

    float acc[4][4][4];
    #pragma unroll
    for (int i = 0; i < 4; i++)
        #pragma unroll
        for (int j = 0; j < 4; j++)
            #pragma unroll
            for (int q = 0; q < 4; q++) acc[i][j][q] = 0.f;

    int nbase[4];
    #pragma unroll
    for (int nt = 0; nt < 4; nt++)
        nbase[nt] = IS_G1 ? ((nt < 2) ? warp_n*16 + nt*8 : 64 + warp_n*16 + (nt-2)*8)
                          : warp_n*32 + nt*8;

    #pragma unroll
    for (int s = 0; s < 4; s++) {
        cp16(aDst + s*ABYT, Aglob + aoff + s*16 + akc, avalid);
        const float* bsrc = Wg + (size_t)(s*16 + bk) * bstride + bcol;
        cp16(bDst + s*BBYT,      bsrc,     16);
        cp16(bDst + s*BBYT + 16, bsrc + 4, 16);
        cp_commit();
    }

    int slc = 0;
    int slp = 4;
    #pragma unroll 1
    for (int it = 0; it < 32; it++) {
        if (it <= 30) cp_wait<2>();
        else cp_wait<0>();
        __syncthreads();

        const int slc1 = (slc == 5) ? 0 : slc + 1;
        if (it <= 29) {
            const int slp1 = (slp == 5) ? 0 : slp + 1;
            const int st = 2*it + 4;
            cp16(aDst + slp*ABYT, Aglob + aoff + st*16 + akc, avalid);
            const float* bsrc = Wg + (size_t)(st*16 + bk) * bstride + bcol;
            cp16(bDst + slp*BBYT,      bsrc,     16);
            cp16(bDst + slp*BBYT + 16, bsrc + 4, 16);
            cp_commit();
            cp16(aDst + slp1*ABYT, Aglob + aoff + (st+1)*16 + akc, avalid);
            bsrc += 16 * bstride;
            cp16(bDst + slp1*BBYT,      bsrc,     16);
            cp16(bDst + slp1*BBYT + 16, bsrc + 4, 16);
            cp_commit();
            slp = (slp1 == 5) ? 0 : slp1 + 1;
        }

        uint32_t bf[2][4][2];
        {
            const float* Bb0 = (const float*)(dsm + OFF_B + slc  * BBYT);
            const float* Bb1 = (const float*)(dsm + OFF_B + slc1 * BBYT);
            #pragma unroll
            for (int nt = 0; nt < 4; nt++) {
                const int nn = nbase[nt] + g;
                bf[0][nt][0] = packh2(Bb0[(2*tg)     * BSTR + nn], Bb0[(2*tg + 1) * BSTR + nn]);
                bf[0][nt][1] = packh2(Bb0[(2*tg + 8) * BSTR + nn], Bb0[(2*tg + 9) * BSTR + nn]);
                bf[1][nt][0] = packh2(Bb1[(2*tg)     * BSTR + nn], Bb1[(2*tg + 1) * BSTR + nn]);
                bf[1][nt][1] = packh2(Bb1[(2*tg + 8) * BSTR + nn], Bb1[(2*tg + 9) * BSTR + nn]);
            }
        }
        {
            const uint32_t aS0 = aFrag + (uint32_t)slc  * ABYT;
            #pragma unroll
            for (int mt = 0; mt < 4; mt++) {
                if (!mv[mt]) continue;
                uint32_t af[4];
                ldsm4(af, aS0 + (uint32_t)mt * (16 * ASTRH * 2));
                #pragma unroll
                for (int nt = 0; nt < 4; nt++)
                    mma16816(acc[mt][nt], af, bf[0][nt]);
            }
        }
        {
            const uint32_t aS1 = aFrag + (uint32_t)slc1 * ABYT;
            #pragma unroll
            for (int mt = 0; mt < 4; mt++) {
                if (!mv[mt]) continue;
                uint32_t af[4];
                ldsm4(af, aS1 + (uint32_t)mt * (16 * ASTRH * 2));
                #pragma unroll
                for (int nt = 0; nt < 4; nt++)
                    mma16816(acc[mt][nt], af, bf[1][nt]);
            }
        }
        slc = (slc1 == 5) ? 0 : slc1 + 1;
    }

    #pragma unroll
    for (int mt = 0; mt < 4; mt++) {
        if (!mv[mt]) continue;
        const int r = warp_m*64 + mt*16 + g;
        const int p0 = spid[r], p1 = spid[r + 8];
        if (IS_G1) {
            #pragma unroll
            for (int nt = 0; nt < 2; nt++) {
                const int il = warp_n*16 + nt*8 + 2*tg;
                const float bg0 = sbias[il], bg1 = sbias[il+1];
                const float bu0 = sbias[64+il], bu1 = sbias[64+il+1];
                #pragma unroll
                for (int h = 0; h < 2; h++) {
                    const int p = h ? p1 : p0;
                    if (p < 0) continue;
                    const float gt0 = fminf(acc[mt][nt][2*h]   + bg0, 7.0f);
                    const float gt1 = fminf(acc[mt][nt][2*h+1] + bg1, 7.0f);
                    const float u0 = fminf(fmaxf(acc[mt][nt+2][2*h]   + bu0, -7.0f), 7.0f);
                    const float u1 = fminf(fmaxf(acc[mt][nt+2][2*h+1] + bu1, -7.0f), 7.0f);
                    const float v0 = (u0 + 1.0f) * gt0 / (1.0f + __expf(-1.702f * gt0));
                    const float v1 = (u1 + 1.0f) * gt1 / (1.0f + __expf(-1.702f * gt1));
                    *(__half2*)(g_acth + (size_t)p * 1024 + c0 + il) =
                        __floats2half2_rn(v0, v1);
                }
            }
        } else {
            const float w0 = swgt[r], w1 = swgt[r + 8];
            #pragma unroll
            for (int nt = 0; nt < 4; nt++) {
                const int cl = warp_n*32 + nt*8 + 2*tg;
                const float b0 = sbias[cl], b1 = sbias[cl+1];
                if (p0 >= 0)
                    *(__half2*)(g_yh + (size_t)p0 * 1024 + c0 + cl) =
                        __floats2half2_rn((acc[mt][nt][0] + b0) * w0,
                                          (acc[mt][nt][1] + b1) * w0);
                if (p1 >= 0)
                    *(__half2*)(g_yh + (size_t)p1 * 1024 + c0 + cl) =
                        __floats2half2_rn((acc[mt][nt][2] + b0) * w1,
                                          (acc[mt][nt][3] + b1) * w1);
            }
        }
    }
}

// ---------------- residual + combine (+ counter reset for next launch) -----
__global__ void k_combine(const float* __restrict__ x, float* __restrict__ out)
{
    const int gid = blockIdx.x * blockDim.x + threadIdx.x;   // over T*H/8
    const int t = gid >> 7, c8 = gid & 127;

    float4 a0 = ((const float4*)x)[gid*2];
    float4 a1 = ((const float4*)x)[gid*2+1];
    #pragma unroll
    for (int k = 0; k < TOPK; k++) {
        const uint4 yv = ((const uint4*)(g_yh + (size_t)(t * TOPK + k) * HDIM))[c8];
        const float2 p0 = __half22float2(*(const __half2*)&yv.x);
        const float2 p1 = __half22float2(*(const __half2*)&yv.y);
        const float2 p2 = __half22float2(*(const __half2*)&yv.z);
        const float2 p3 = __half22float2(*(const __half2*)&yv.w);
        a0.x += p0.x; a0.y += p0.y; a0.z += p1.x; a0.w += p1.y;
        a1.x += p2.x; a1.y += p2.y; a1.z += p3.x; a1.w += p3.y;
    }
    ((float4*)out)[gid*2]   = a0;
    ((float4*)out)[gid*2+1] = a1;

    if (gid < NEXP) g_cnt[gid] = 0;
}

extern "C" void kernel_launch(void* const* d_in, const int* in_sizes, int n_in,
                              void* d_out, int out_size)
{
    const float* x   = (const float*)d_in[0];
    const float* nw  = (const float*)d_in[1];
    const float* rw  = (const float*)d_in[2];
    const float* rb  = (const float*)d_in[3];
    const float* w13 = (const float*)d_in[4];
    const float* b13 = (const float*)d_in[5];
    const float* w2  = (const float*)d_in[6];
    const float* b2  = (const float*)d_in[7];
    const float* mw  = (const float*)d_in[8];
    const int*   li  = (n_in >= 10) ? (const int*)d_in[9] : nullptr;
    float* out = (float*)d_out;

    cudaFuncSetAttribute((const void*)k_mma<1>,
                         cudaFuncAttributeMaxDynamicSharedMemorySize, SMEM_MMA);
    cudaFuncSetAttribute((const void*)k_mma<0>,
                         cudaFuncAttributeMaxDynamicSharedMemorySize, SMEM_MMA);

    k_norm_router<<<T_TOK, 256>>>(x, nw, rw, rb, mw, li);
    k_mma<1><<<dim3(16, 8, NEXP), 256, SMEM_MMA>>>(w13, b13);
    k_mma<0><<<dim3(8, 8, NEXP), 256, SMEM_MMA>>>(w2, b2);
    k_combine<<<(T_TOK * HDIM / 8) / 256, 256>>>(x, out);
}

// round 15
// speedup vs baseline: 1.0123x; 1.0123x over previous
#include <cuda_runtime.h>
#include <cuda_fp16.h>
#include <cstdint>
#include <math.h>

#define T_TOK 1024
#define HDIM  1024
#define NEXP  16
#define TOPK  4
#define NPAIR (T_TOK*TOPK)

__device__ __half g_tnormh[T_TOK*HDIM];
__device__ __half g_acth[NPAIR*HDIM];
__device__ __half g_yh[NPAIR*HDIM];
__device__ float  g_wgt[NPAIR];
__device__ int    g_plist[NEXP*T_TOK];
__device__ int    g_cnt[NEXP];          // zero-init at load; re-zeroed by k_combine

// ---------------- helpers ----------------
__device__ __forceinline__ uint32_t smem_u32(const void* p) {
    uint32_t a;
    asm("{ .reg .u64 t; cvta.to.shared.u64 t, %1; cvt.u32.u64 %0, t; }" : "=r"(a) : "l"(p));
    return a;
}
__device__ __forceinline__ void cp16(uint32_t dst, const void* src, int srcbytes) {
    asm volatile("cp.async.cg.shared.global [%0], [%1], 16, %2;"
                 :: "r"(dst), "l"(src), "r"(srcbytes) : "memory");
}
__device__ __forceinline__ void cp_commit() {
    asm volatile("cp.async.commit_group;" ::: "memory");
}
template<int N> __device__ __forceinline__ void cp_wait() {
    asm volatile("cp.async.wait_group %0;" :: "n"(N) : "memory");
}
__device__ __forceinline__ uint32_t packh2(float lo, float hi) {
    uint32_t r;
    asm("cvt.rn.f16x2.f32 %0, %1, %2;" : "=r"(r) : "f"(hi), "f"(lo));
    return r;
}
__device__ __forceinline__ void ldsm4(uint32_t* r, uint32_t a) {
    asm volatile("ldmatrix.sync.aligned.m8n8.x4.shared.b16 {%0,%1,%2,%3}, [%4];"
                 : "=r"(r[0]), "=r"(r[1]), "=r"(r[2]), "=r"(r[3]) : "r"(a));
}
__device__ __forceinline__ void mma16816(float* d, const uint32_t* a, const uint32_t* b) {
    asm volatile("mma.sync.aligned.m16n8k16.row.col.f32.f16.f16.f32 "
                 "{%0,%1,%2,%3}, {%4,%5,%6,%7}, {%8,%9}, {%0,%1,%2,%3};"
                 : "+f"(d[0]), "+f"(d[1]), "+f"(d[2]), "+f"(d[3])
                 : "r"(a[0]), "r"(a[1]), "r"(a[2]), "r"(a[3]), "r"(b[0]), "r"(b[1]));
}

// ---------------- RMSNorm + router + top-4 + dispatch ----------------
__global__ void k_norm_router(const float* __restrict__ x, const float* __restrict__ nw,
                              const float* __restrict__ rw, const float* __restrict__ rb,
                              const float* __restrict__ mw, const int* __restrict__ lip)
{
    const int t = blockIdx.x, tid = threadIdx.x;
    const int wid = tid >> 5, lane = tid & 31;

    float4 xv = ((const float4*)(x + (size_t)t * HDIM))[tid];
    float ss = xv.x*xv.x + xv.y*xv.y + xv.z*xv.z + xv.w*xv.w;

    __shared__ float sw8[8];
    #pragma unroll
    for (int o = 16; o; o >>= 1) ss += __shfl_xor_sync(~0u, ss, o);
    if (lane == 0) sw8[wid] = ss;
    __syncthreads();
    __shared__ float s_scale;
    if (tid == 0) {
        float tot = 0.f;
        #pragma unroll
        for (int i = 0; i < 8; i++) tot += sw8[i];
        s_scale = rsqrtf(tot / (float)HDIM + 1e-5f);
    }
    __syncthreads();
    const float s = s_scale;

    float4 nv = ((const float4*)nw)[tid];
    float4 tv = make_float4(xv.x*s*nv.x, xv.y*s*nv.y, xv.z*s*nv.z, xv.w*s*nv.w);
    {
        __half2* th = (__half2*)(g_tnormh + (size_t)t * HDIM);
        th[tid*2]   = __floats2half2_rn(tv.x, tv.y);
        th[tid*2+1] = __floats2half2_rn(tv.z, tv.w);
    }

    float p[NEXP];
    #pragma unroll
    for (int e = 0; e < NEXP; e++) {
        float4 wv = ((const float4*)(rw + (size_t)e * HDIM))[tid];
        p[e] = tv.x*wv.x + tv.y*wv.y + tv.z*wv.z + tv.w*wv.w;
    }
    __shared__ float sall[8][NEXP];
    #pragma unroll
    for (int e = 0; e < NEXP; e++) {
        float v = p[e];
        #pragma unroll
        for (int o = 16; o; o >>= 1) v += __shfl_xor_sync(~0u, v, o);
        if (lane == 0) sall[wid][e] = v;
    }
    __syncthreads();

    if (tid == 0) {
        float g[NEXP];
        #pragma unroll
        for (int e = 0; e < NEXP; e++) {
            float v = 0.f;
            #pragma unroll
            for (int w = 0; w < 8; w++) v += sall[w][e];
            g[e] = v + rb[e];
        }
        const int li = lip ? lip[0] : 0;
        float ma = 0.f;
        #pragma unroll
        for (int e = 0; e < NEXP; e++) ma = fmaxf(ma, fabsf(mw[li*NEXP + e]));
        if (ma > 0.f) {
            float m = -1e30f;
            for (int e = 0; e < NEXP; e++) m = fmaxf(m, g[e]);
            float se = 0.f;
            for (int e = 0; e < NEXP; e++) se += expf(g[e] - m);
            const float lse = m + logf(se);
            float gl[NEXP], mx = -1e30f, mn = 1e30f;
            for (int e = 0; e < NEXP; e++) {
                gl[e] = g[e] - lse;
                mx = fmaxf(mx, gl[e]); mn = fminf(mn, gl[e]);
            }
            for (int e = 0; e < NEXP; e++) {
                const float l = mw[li*NEXP + e];
                g[e] = (l > 0.f) ? mx + 0.01f : (l < 0.f) ? mn - 0.01f : gl[e];
            }
        }
        int idx[TOPK]; float val[TOPK]; unsigned used = 0;
        #pragma unroll
        for (int k = 0; k < TOPK; k++) {
            int b = 0; float bv = -1e38f;
            for (int e = 0; e < NEXP; e++)
                if (!((used >> e) & 1u) && g[e] > bv) { bv = g[e]; b = e; }
            used |= 1u << b; idx[k] = b; val[k] = bv;
        }
        const float m0 = val[0];
        float wsum = 0.f, wv2[TOPK];
        #pragma unroll
        for (int k = 0; k < TOPK; k++) { wv2[k] = expf(val[k] - m0); wsum += wv2[k]; }
        #pragma unroll
        for (int k = 0; k < TOPK; k++) {
            const int e = idx[k];
            const int pos = atomicAdd(&g_cnt[e], 1);
            g_plist[e * T_TOK + pos] = t * TOPK + k;
            g_wgt[t * TOPK + k] = wv2[k] / wsum;
        }
    }
}

// ---------------- fp16 mma GEMM (R13 structure; G2 now 64-col x-blocks) ----
#define NSTG  6
#define ASTRH 24
#define ABYT  (128*ASTRH*2)          // 6144 B per A stage

// per-variant B geometry
#define BSTR_G1  132
#define BSTR_G2  68
#define BBYT_G1  (16*BSTR_G1*4)      // 8448
#define BBYT_G2  (16*BSTR_G2*4)      // 4352
#define SMEM_G1  (NSTG*(ABYT + BBYT_G1))   // 87552
#define SMEM_G2  (NSTG*(ABYT + BBYT_G2))   // 62976

template<int IS_G1>
__global__ __launch_bounds__(256, 2)
void k_mma(const float* __restrict__ W, const float* __restrict__ bias)
{
    constexpr int NTT   = IS_G1 ? 4 : 2;           // nt tiles per warp
    constexpr int BSTRX = IS_G1 ? BSTR_G1 : BSTR_G2;
    constexpr int BBYTX = 16 * BSTRX * 4;
    constexpr int OFF_BX = NSTG * ABYT;

    const int e = blockIdx.z;
    const int n = g_cnt[e];
    const int row0 = blockIdx.y * 128;
    if (row0 >= n) return;

    extern __shared__ char dsm[];
    __shared__ float sbias[128];
    __shared__ int   spid[128];
    __shared__ float swgt[128];

    const int tid = threadIdx.x, lane = tid & 31, wid = tid >> 5;
    const int g = lane >> 2, tg = lane & 3;
    const int warp_m = wid >> 2, warp_n = wid & 3;
    const int c0 = blockIdx.x * 64;                // 64 output cols for both

    if (tid < 128) {
        const int r = row0 + tid;
        const int p = (r < n) ? g_plist[e * T_TOK + r] : -1;
        spid[tid] = p;
        if (!IS_G1) swgt[tid] = (p >= 0) ? g_wgt[p] : 0.f;
        if (IS_G1)
            sbias[tid] = (tid < 64) ? bias[e*2048 + c0 + tid]
                                    : bias[e*2048 + 1024 + c0 + (tid - 64)];
        else if (tid < 64)
            sbias[tid] = bias[e*1024 + c0 + tid];
    }
    __syncthreads();

    const __half* Aglob = IS_G1 ? g_tnormh : g_acth;
    const int arow = tid >> 1;
    const int akc  = (tid & 1) * 8;
    const int apid = spid[arow];
    const long aoff = (apid < 0) ? 0 : (IS_G1 ? (long)(apid >> 2) * HDIM : (long)apid * HDIM);
    const int avalid = (apid >= 0) ? 16 : 0;

    const int bk  = tid >> 4;                          // k row 0..15
    const int bcl = (tid & 15) * (IS_G1 ? 8 : 4);      // f32 smem col
    const long bstride = IS_G1 ? 2048 : 1024;
    const float* Wg = W + (size_t)e * (size_t)bstride * 1024;
    long bcol;
    if (IS_G1) bcol = (bcl < 64) ? (long)(c0 + bcl) : (long)(1024 + c0 + (bcl - 64));
    else       bcol = (long)(c0 + bcl);

    const uint32_t sBase = smem_u32(dsm);
    const uint32_t aDst = sBase + (uint32_t)(arow * ASTRH + akc) * 2;
    const uint32_t bDst = sBase + OFF_BX + (uint32_t)(bk * BSTRX + bcl) * 4;

    const int a_rin = ((lane >> 3) & 1) * 8 + (lane & 7);
    const uint32_t aFrag = sBase + (uint32_t)((warp_m*64 + a_rin) * ASTRH) * 2
                         + (uint32_t)(lane >> 4) * 16;

    float acc[4][NTT][4];
    #pragma unroll
    for (int i = 0; i < 4; i++)
        #pragma unroll
        for (int j = 0; j < NTT; j++)
            #pragma unroll
            for (int q = 0; q < 4; q++) acc[i][j][q] = 0.f;

    int nbase[NTT];
    #pragma unroll
    for (int nt = 0; nt < NTT; nt++)
        nbase[nt] = IS_G1 ? ((nt < 2) ? warp_n*16 + nt*8 : 64 + warp_n*16 + (nt-2)*8)
                          : warp_n*16 + nt*8;

    #pragma unroll
    for (int s = 0; s < 4; s++) {
        cp16(aDst + s*ABYT, Aglob + aoff + s*16 + akc, avalid);
        const float* bsrc = Wg + (size_t)(s*16 + bk) * bstride + bcol;
        cp16(bDst + s*BBYTX, bsrc, 16);
        if (IS_G1) cp16(bDst + s*BBYTX + 16, bsrc + 4, 16);
        cp_commit();
    }

    int slc = 0;
    int slp = 4;
    #pragma unroll 1
    for (int it = 0; it < 32; it++) {
        if (it <= 30) cp_wait<2>();
        else cp_wait<0>();
        __syncthreads();

        const int slc1 = (slc == 5) ? 0 : slc + 1;
        if (it <= 29) {
            const int slp1 = (slp == 5) ? 0 : slp + 1;
            const int st = 2*it + 4;
            cp16(aDst + slp*ABYT, Aglob + aoff + st*16 + akc, avalid);
            const float* bsrc = Wg + (size_t)(st*16 + bk) * bstride + bcol;
            cp16(bDst + slp*BBYTX, bsrc, 16);
            if (IS_G1) cp16(bDst + slp*BBYTX + 16, bsrc + 4, 16);
            cp_commit();
            cp16(aDst + slp1*ABYT, Aglob + aoff + (st+1)*16 + akc, avalid);
            bsrc += 16 * bstride;
            cp16(bDst + slp1*BBYTX, bsrc, 16);
            if (IS_G1) cp16(bDst + slp1*BBYTX + 16, bsrc + 4, 16);
            cp_commit();
            slp = (slp1 == 5) ? 0 : slp1 + 1;
        }

        uint32_t bf[2][NTT][2];
        {
            const float* Bb0 = (const float*)(dsm + OFF_BX + slc  * BBYTX);
            const float* Bb1 = (const float*)(dsm + OFF_BX + slc1 * BBYTX);
            #pragma unroll
            for (int nt = 0; nt < NTT; nt++) {
                const int nn = nbase[nt] + g;
                bf[0][nt][0] = packh2(Bb0[(2*tg)     * BSTRX + nn], Bb0[(2*tg + 1) * BSTRX + nn]);
                bf[0][nt][1] = packh2(Bb0[(2*tg + 8) * BSTRX + nn], Bb0[(2*tg + 9) * BSTRX + nn]);
                bf[1][nt][0] = packh2(Bb1[(2*tg)     * BSTRX + nn], Bb1[(2*tg + 1) * BSTRX + nn]);
                bf[1][nt][1] = packh2(Bb1[(2*tg + 8) * BSTRX + nn], Bb1[(2*tg + 9) * BSTRX + nn]);
            }
        }
        {
            const uint32_t aS0 = aFrag + (uint32_t)slc  * ABYT;
            uint32_t af[4][4];
            #pragma unroll
            for (int mt = 0; mt < 4; mt++)
                ldsm4(af[mt], aS0 + (uint32_t)mt * (16 * ASTRH * 2));
            #pragma unroll
            for (int mt = 0; mt < 4; mt++)
                #pragma unroll
                for (int nt = 0; nt < NTT; nt++)
                    mma16816(acc[mt][nt], af[mt], bf[0][nt]);
        }
        {
            const uint32_t aS1 = aFrag + (uint32_t)slc1 * ABYT;
            uint32_t af[4][4];
            #pragma unroll
            for (int mt = 0; mt < 4; mt++)
                ldsm4(af[mt], aS1 + (uint32_t)mt * (16 * ASTRH * 2));
            #pragma unroll
            for (int mt = 0; mt < 4; mt++)
                #pragma unroll
                for (int nt = 0; nt < NTT; nt++)
                    mma16816(acc[mt][nt], af[mt], bf[1][nt]);
        }
        slc = (slc1 == 5) ? 0 : slc1 + 1;
    }

    #pragma unroll
    for (int mt = 0; mt < 4; mt++) {
        const int r = warp_m*64 + mt*16 + g;
        const int p0 = spid[r], p1 = spid[r + 8];
        if (IS_G1) {
            #pragma unroll
            for (int nt = 0; nt < 2; nt++) {
                const int il = warp_n*16 + nt*8 + 2*tg;
                const float bg0 = sbias[il], bg1 = sbias[il+1];
                const float bu0 = sbias[64+il], bu1 = sbias[64+il+1];
                #pragma unroll
                for (int h = 0; h < 2; h++) {
                    const int p = h ? p1 : p0;
                    if (p < 0) continue;
                    const float gt0 = fminf(acc[mt][nt][2*h]   + bg0, 7.0f);
                    const float gt1 = fminf(acc[mt][nt][2*h+1] + bg1, 7.0f);
                    const float u0 = fminf(fmaxf(acc[mt][nt+2][2*h]   + bu0, -7.0f), 7.0f);
                    const float u1 = fminf(fmaxf(acc[mt][nt+2][2*h+1] + bu1, -7.0f), 7.0f);
                    const float v0 = (u0 + 1.0f) * gt0 / (1.0f + __expf(-1.702f * gt0));
                    const float v1 = (u1 + 1.0f) * gt1 / (1.0f + __expf(-1.702f * gt1));
                    *(__half2*)(g_acth + (size_t)p * 1024 + c0 + il) =
                        __floats2half2_rn(v0, v1);
                }
            }
        } else {
            const float w0 = swgt[r], w1 = swgt[r + 8];
            #pragma unroll
            for (int nt = 0; nt < NTT; nt++) {
                const int cl = warp_n*16 + nt*8 + 2*tg;
                const float b0 = sbias[cl], b1 = sbias[cl+1];
                if (p0 >= 0)
                    *(__half2*)(g_yh + (size_t)p0 * 1024 + c0 + cl) =
                        __floats2half2_rn((acc[mt][nt][0] + b0) * w0,
                                          (acc[mt][nt][1] + b1) * w0);
                if (p1 >= 0)
                    *(__half2*)(g_yh + (size_t)p1 * 1024 + c0 + cl) =
                        __floats2half2_rn((acc[mt][nt][2] + b0) * w1,
                                          (acc[mt][nt][3] + b1) * w1);
            }
        }
    }
}

// ---------------- residual + combine (+ counter reset for next launch) -----
__global__ void k_combine(const float* __restrict__ x, float* __restrict__ out)
{
    const int gid = blockIdx.x * blockDim.x + threadIdx.x;   // over T*H/8
    const int t = gid >> 7, c8 = gid & 127;

    float4 a0 = ((const float4*)x)[gid*2];
    float4 a1 = ((const float4*)x)[gid*2+1];
    #pragma unroll
    for (int k = 0; k < TOPK; k++) {
        const uint4 yv = ((const uint4*)(g_yh + (size_t)(t * TOPK + k) * HDIM))[c8];
        const float2 p0 = __half22float2(*(const __half2*)&yv.x);
        const float2 p1 = __half22float2(*(const __half2*)&yv.y);
        const float2 p2 = __half22float2(*(const __half2*)&yv.z);
        const float2 p3 = __half22float2(*(const __half2*)&yv.w);
        a0.x += p0.x; a0.y += p0.y; a0.z += p1.x; a0.w += p1.y;
        a1.x += p2.x; a1.y += p2.y; a1.z += p3.x; a1.w += p3.y;
    }
    ((float4*)out)[gid*2]   = a0;
    ((float4*)out)[gid*2+1] = a1;

    if (gid < NEXP) g_cnt[gid] = 0;
}

extern "C" void kernel_launch(void* const* d_in, const int* in_sizes, int n_in,
                              void* d_out, int out_size)
{
    const float* x   = (const float*)d_in[0];
    const float* nw  = (const float*)d_in[1];
    const float* rw  = (const float*)d_in[2];
    const float* rb  = (const float*)d_in[3];
    const float* w13 = (const float*)d_in[4];
    const float* b13 = (const float*)d_in[5];
    const float* w2  = (const float*)d_in[6];
    const float* b2  = (const float*)d_in[7];
    const float* mw  = (const float*)d_in[8];
    const int*   li  = (n_in >= 10) ? (const int*)d_in[9] : nullptr;
    float* out = (float*)d_out;

    cudaFuncSetAttribute((const void*)k_mma<1>,
                         cudaFuncAttributeMaxDynamicSharedMemorySize, SMEM_G1);
    cudaFuncSetAttribute((const void*)k_mma<0>,
                         cudaFuncAttributeMaxDynamicSharedMemorySize, SMEM_G2);

    k_norm_router<<<T_TOK, 256>>>(x, nw, rw, rb, mw, li);
    k_mma<1><<<dim3(16, 8, NEXP), 256, SMEM_G1>>>(w13, b13);
    k_mma<0><<<dim3(16, 8, NEXP), 256, SMEM_G2>>>(w2, b2);
    k_combine<<<(T_TOK * HDIM / 8) / 256, 256>>>(x, out);
}

// round 16
// speedup vs baseline: 1.0408x; 1.0282x over previous
#include <cuda_runtime.h>
#include <cuda_fp16.h>
#include <cstdint>
#include <math.h>

#define T_TOK 1024
#define HDIM  1024
#define NEXP  16
#define TOPK  4
#define NPAIR (T_TOK*TOPK)

__device__ __half g_tnormh[T_TOK*HDIM];
__device__ __half g_acth[NPAIR*HDIM];
__device__ __half g_yh[NPAIR*HDIM];
__device__ float  g_wgt[NPAIR];
__device__ int    g_plist[NEXP*T_TOK];
__device__ int    g_cnt[NEXP];          // zero-init at load; re-zeroed by k_combine

// ---------------- helpers ----------------
__device__ __forceinline__ uint32_t smem_u32(const void* p) {
    uint32_t a;
    asm("{ .reg .u64 t; cvta.to.shared.u64 t, %1; cvt.u32.u64 %0, t; }" : "=r"(a) : "l"(p));
    return a;
}
__device__ __forceinline__ void cp16(uint32_t dst, const void* src, int srcbytes) {
    asm volatile("cp.async.cg.shared.global [%0], [%1], 16, %2;"
                 :: "r"(dst), "l"(src), "r"(srcbytes) : "memory");
}
__device__ __forceinline__ void cp_commit() {
    asm volatile("cp.async.commit_group;" ::: "memory");
}
template<int N> __device__ __forceinline__ void cp_wait() {
    asm volatile("cp.async.wait_group %0;" :: "n"(N) : "memory");
}
__device__ __forceinline__ uint32_t packh2(float lo, float hi) {
    uint32_t r;
    asm("cvt.rn.f16x2.f32 %0, %1, %2;" : "=r"(r) : "f"(hi), "f"(lo));
    return r;
}
__device__ __forceinline__ void ldsm4(uint32_t* r, uint32_t a) {
    asm volatile("ldmatrix.sync.aligned.m8n8.x4.shared.b16 {%0,%1,%2,%3}, [%4];"
                 : "=r"(r[0]), "=r"(r[1]), "=r"(r[2]), "=r"(r[3]) : "r"(a));
}
__device__ __forceinline__ void mma16816(float* d, const uint32_t* a, const uint32_t* b) {
    asm volatile("mma.sync.aligned.m16n8k16.row.col.f32.f16.f16.f32 "
                 "{%0,%1,%2,%3}, {%4,%5,%6,%7}, {%8,%9}, {%0,%1,%2,%3};"
                 : "+f"(d[0]), "+f"(d[1]), "+f"(d[2]), "+f"(d[3])
                 : "r"(a[0]), "r"(a[1]), "r"(a[2]), "r"(a[3]), "r"(b[0]), "r"(b[1]));
}

// ---------------- RMSNorm + router + top-4 + dispatch ----------------
__global__ void k_norm_router(const float* __restrict__ x, const float* __restrict__ nw,
                              const float* __restrict__ rw, const float* __restrict__ rb,
                              const float* __restrict__ mw, const int* __restrict__ lip)
{
    const int t = blockIdx.x, tid = threadIdx.x;
    const int wid = tid >> 5, lane = tid & 31;

    float4 xv = ((const float4*)(x + (size_t)t * HDIM))[tid];
    float ss = xv.x*xv.x + xv.y*xv.y + xv.z*xv.z + xv.w*xv.w;

    __shared__ float sw8[8];
    #pragma unroll
    for (int o = 16; o; o >>= 1) ss += __shfl_xor_sync(~0u, ss, o);
    if (lane == 0) sw8[wid] = ss;
    __syncthreads();
    __shared__ float s_scale;
    if (tid == 0) {
        float tot = 0.f;
        #pragma unroll
        for (int i = 0; i < 8; i++) tot += sw8[i];
        s_scale = rsqrtf(tot / (float)HDIM + 1e-5f);
    }
    __syncthreads();
    const float s = s_scale;

    float4 nv = ((const float4*)nw)[tid];
    float4 tv = make_float4(xv.x*s*nv.x, xv.y*s*nv.y, xv.z*s*nv.z, xv.w*s*nv.w);
    {
        __half2* th = (__half2*)(g_tnormh + (size_t)t * HDIM);
        th[tid*2]   = __floats2half2_rn(tv.x, tv.y);
        th[tid*2+1] = __floats2half2_rn(tv.z, tv.w);
    }

    float p[NEXP];
    #pragma unroll
    for (int e = 0; e < NEXP; e++) {
        float4 wv = ((const float4*)(rw + (size_t)e * HDIM))[tid];
        p[e] = tv.x*wv.x + tv.y*wv.y + tv.z*wv.z + tv.w*wv.w;
    }
    __shared__ float sall[8][NEXP];
    #pragma unroll
    for (int e = 0; e < NEXP; e++) {
        float v = p[e];
        #pragma unroll
        for (int o = 16; o; o >>= 1) v += __shfl_xor_sync(~0u, v, o);
        if (lane == 0) sall[wid][e] = v;
    }
    __syncthreads();

    if (tid == 0) {
        float g[NEXP];
        #pragma unroll
        for (int e = 0; e < NEXP; e++) {
            float v = 0.f;
            #pragma unroll
            for (int w = 0; w < 8; w++) v += sall[w][e];
            g[e] = v + rb[e];
        }
        const int li = lip ? lip[0] : 0;
        float ma = 0.f;
        #pragma unroll
        for (int e = 0; e < NEXP; e++) ma = fmaxf(ma, fabsf(mw[li*NEXP + e]));
        if (ma > 0.f) {
            float m = -1e30f;
            for (int e = 0; e < NEXP; e++) m = fmaxf(m, g[e]);
            float se = 0.f;
            for (int e = 0; e < NEXP; e++) se += expf(g[e] - m);
            const float lse = m + logf(se);
            float gl[NEXP], mx = -1e30f, mn = 1e30f;
            for (int e = 0; e < NEXP; e++) {
                gl[e] = g[e] - lse;
                mx = fmaxf(mx, gl[e]); mn = fminf(mn, gl[e]);
            }
            for (int e = 0; e < NEXP; e++) {
                const float l = mw[li*NEXP + e];
                g[e] = (l > 0.f) ? mx + 0.01f : (l < 0.f) ? mn - 0.01f : gl[e];
            }
        }
        int idx[TOPK]; float val[TOPK]; unsigned used = 0;
        #pragma unroll
        for (int k = 0; k < TOPK; k++) {
            int b = 0; float bv = -1e38f;
            for (int e = 0; e < NEXP; e++)
                if (!((used >> e) & 1u) && g[e] > bv) { bv = g[e]; b = e; }
            used |= 1u << b; idx[k] = b; val[k] = bv;
        }
        const float m0 = val[0];
        float wsum = 0.f, wv2[TOPK];
        #pragma unroll
        for (int k = 0; k < TOPK; k++) { wv2[k] = expf(val[k] - m0); wsum += wv2[k]; }
        #pragma unroll
        for (int k = 0; k < TOPK; k++) {
            const int e = idx[k];
            const int pos = atomicAdd(&g_cnt[e], 1);
            g_plist[e * T_TOK + pos] = t * TOPK + k;
            g_wgt[t * TOPK + k] = wv2[k] / wsum;
        }
    }
}

// ---------------- fp16 mma GEMM (R13 best configuration) -------------------
#define NSTG  6
#define ASTRH 24
#define ABYT  (128*ASTRH*2)
#define BSTR  132
#define BBYT  (16*BSTR*4)
#define OFF_B (NSTG*ABYT)
#define SMEM_MMA (NSTG*(ABYT + BBYT))   // 87552 B

template<int IS_G1>
__global__ __launch_bounds__(256, 2)
void k_mma(const float* __restrict__ W, const float* __restrict__ bias)
{
    const int e = blockIdx.z;
    const int n = g_cnt[e];
    const int row0 = blockIdx.y * 128;
    if (row0 >= n) return;

    extern __shared__ char dsm[];
    __shared__ float sbias[128];
    __shared__ int   spid[128];
    __shared__ float swgt[128];

    const int tid = threadIdx.x, lane = tid & 31, wid = tid >> 5;
    const int g = lane >> 2, tg = lane & 3;
    const int warp_m = wid >> 2, warp_n = wid & 3;
    const int c0 = blockIdx.x * (IS_G1 ? 64 : 128);

    if (tid < 128) {
        const int r = row0 + tid;
        const int p = (r < n) ? g_plist[e * T_TOK + r] : -1;
        spid[tid] = p;
        if (!IS_G1) swgt[tid] = (p >= 0) ? g_wgt[p] : 0.f;
        if (IS_G1)
            sbias[tid] = (tid < 64) ? bias[e*2048 + c0 + tid]
                                    : bias[e*2048 + 1024 + c0 + (tid - 64)];
        else
            sbias[tid] = bias[e*1024 + c0 + tid];
    }
    __syncthreads();

    const __half* Aglob = IS_G1 ? g_tnormh : g_acth;
    const int arow = tid >> 1;
    const int akc  = (tid & 1) * 8;
    const int apid = spid[arow];
    const long aoff = (apid < 0) ? 0 : (IS_G1 ? (long)(apid >> 2) * HDIM : (long)apid * HDIM);
    const int avalid = (apid >= 0) ? 16 : 0;

    const int bk  = tid >> 4;
    const int bcl = (tid & 15) * 8;
    const long bstride = IS_G1 ? 2048 : 1024;
    const float* Wg = W + (size_t)e * (size_t)bstride * 1024;
    long bcol;
    if (IS_G1) bcol = (bcl < 64) ? (long)(c0 + bcl) : (long)(1024 + c0 + (bcl - 64));
    else       bcol = (long)(c0 + bcl);

    const uint32_t sBase = smem_u32(dsm);
    const uint32_t aDst = sBase + (uint32_t)(arow * ASTRH + akc) * 2;
    const uint32_t bDst = sBase + OFF_B + (uint32_t)(bk * BSTR + bcl) * 4;

    const int a_rin = ((lane >> 3) & 1) * 8 + (lane & 7);
    const uint32_t aFrag = sBase + (uint32_t)((warp_m*64 + a_rin) * ASTRH) * 2
                         + (uint32_t)(lane >> 4) * 16;

    float acc[4][4][4];
    #pragma unroll
    for (int i = 0; i < 4; i++)
        #pragma unroll
        for (int j = 0; j < 4; j++)
            #pragma unroll
            for (int q = 0; q < 4; q++) acc[i][j][q] = 0.f;

    int nbase[4];
    #pragma unroll
    for (int nt = 0; nt < 4; nt++)
        nbase[nt] = IS_G1 ? ((nt < 2) ? warp_n*16 + nt*8 : 64 + warp_n*16 + (nt-2)*8)
                          : warp_n*32 + nt*8;

    #pragma unroll
    for (int s = 0; s < 4; s++) {
        cp16(aDst + s*ABYT, Aglob + aoff + s*16 + akc, avalid);
        const float* bsrc = Wg + (size_t)(s*16 + bk) * bstride + bcol;
        cp16(bDst + s*BBYT,      bsrc,     16);
        cp16(bDst + s*BBYT + 16, bsrc + 4, 16);
        cp_commit();
    }

    int slc = 0;
    int slp = 4;
    #pragma unroll 1
    for (int it = 0; it < 32; it++) {
        if (it <= 30) cp_wait<2>();
        else cp_wait<0>();
        __syncthreads();

        const int slc1 = (slc == 5) ? 0 : slc + 1;
        if (it <= 29) {
            const int slp1 = (slp == 5) ? 0 : slp + 1;
            const int st = 2*it + 4;
            cp16(aDst + slp*ABYT, Aglob + aoff + st*16 + akc, avalid);
            const float* bsrc = Wg + (size_t)(st*16 + bk) * bstride + bcol;
            cp16(bDst + slp*BBYT,      bsrc,     16);
            cp16(bDst + slp*BBYT + 16, bsrc + 4, 16);
            cp_commit();
            cp16(aDst + slp1*ABYT, Aglob + aoff + (st+1)*16 + akc, avalid);
            bsrc += 16 * bstride;
            cp16(bDst + slp1*BBYT,      bsrc,     16);
            cp16(bDst + slp1*BBYT + 16, bsrc + 4, 16);
            cp_commit();
            slp = (slp1 == 5) ? 0 : slp1 + 1;
        }

        uint32_t bf[2][4][2];
        {
            const float* Bb0 = (const float*)(dsm + OFF_B + slc  * BBYT);
            const float* Bb1 = (const float*)(dsm + OFF_B + slc1 * BBYT);
            #pragma unroll
            for (int nt = 0; nt < 4; nt++) {
                const int nn = nbase[nt] + g;
                bf[0][nt][0] = packh2(Bb0[(2*tg)     * BSTR + nn], Bb0[(2*tg + 1) * BSTR + nn]);
                bf[0][nt][1] = packh2(Bb0[(2*tg + 8) * BSTR + nn], Bb0[(2*tg + 9) * BSTR + nn]);
                bf[1][nt][0] = packh2(Bb1[(2*tg)     * BSTR + nn], Bb1[(2*tg + 1) * BSTR + nn]);
                bf[1][nt][1] = packh2(Bb1[(2*tg + 8) * BSTR + nn], Bb1[(2*tg + 9) * BSTR + nn]);
            }
        }
        {
            const uint32_t aS0 = aFrag + (uint32_t)slc  * ABYT;
            uint32_t af[4][4];
            #pragma unroll
            for (int mt = 0; mt < 4; mt++)
                ldsm4(af[mt], aS0 + (uint32_t)mt * (16 * ASTRH * 2));
            #pragma unroll
            for (int mt = 0; mt < 4; mt++)
                #pragma unroll
                for (int nt = 0; nt < 4; nt++)
                    mma16816(acc[mt][nt], af[mt], bf[0][nt]);
        }
        {
            const uint32_t aS1 = aFrag + (uint32_t)slc1 * ABYT;
            uint32_t af[4][4];
            #pragma unroll
            for (int mt = 0; mt < 4; mt++)
                ldsm4(af[mt], aS1 + (uint32_t)mt * (16 * ASTRH * 2));
            #pragma unroll
            for (int mt = 0; mt < 4; mt++)
                #pragma unroll
                for (int nt = 0; nt < 4; nt++)
                    mma16816(acc[mt][nt], af[mt], bf[1][nt]);
        }
        slc = (slc1 == 5) ? 0 : slc1 + 1;
    }

    #pragma unroll
    for (int mt = 0; mt < 4; mt++) {
        const int r = warp_m*64 + mt*16 + g;
        const int p0 = spid[r], p1 = spid[r + 8];
        if (IS_G1) {
            #pragma unroll
            for (int nt = 0; nt < 2; nt++) {
                const int il = warp_n*16 + nt*8 + 2*tg;
                const float bg0 = sbias[il], bg1 = sbias[il+1];
                const float bu0 = sbias[64+il], bu1 = sbias[64+il+1];
                #pragma unroll
                for (int h = 0; h < 2; h++) {
                    const int p = h ? p1 : p0;
                    if (p < 0) continue;
                    const float gt0 = fminf(acc[mt][nt][2*h]   + bg0, 7.0f);
                    const float gt1 = fminf(acc[mt][nt][2*h+1] + bg1, 7.0f);
                    const float u0 = fminf(fmaxf(acc[mt][nt+2][2*h]   + bu0, -7.0f), 7.0f);
                    const float u1 = fminf(fmaxf(acc[mt][nt+2][2*h+1] + bu1, -7.0f), 7.0f);
                    const float v0 = (u0 + 1.0f) * gt0 / (1.0f + __expf(-1.702f * gt0));
                    const float v1 = (u1 + 1.0f) * gt1 / (1.0f + __expf(-1.702f * gt1));
                    *(__half2*)(g_acth + (size_t)p * 1024 + c0 + il) =
                        __floats2half2_rn(v0, v1);
                }
            }
        } else {
            const float w0 = swgt[r], w1 = swgt[r + 8];
            #pragma unroll
            for (int nt = 0; nt < 4; nt++) {
                const int cl = warp_n*32 + nt*8 + 2*tg;
                const float b0 = sbias[cl], b1 = sbias[cl+1];
                if (p0 >= 0)
                    *(__half2*)(g_yh + (size_t)p0 * 1024 + c0 + cl) =
                        __floats2half2_rn((acc[mt][nt][0] + b0) * w0,
                                          (acc[mt][nt][1] + b1) * w0);
                if (p1 >= 0)
                    *(__half2*)(g_yh + (size_t)p1 * 1024 + c0 + cl) =
                        __floats2half2_rn((acc[mt][nt][2] + b0) * w1,
                                          (acc[mt][nt][3] + b1) * w1);
            }
        }
    }
}

// ---------------- residual + combine (+ counter reset for next launch) -----
__global__ void k_combine(const float* __restrict__ x, float* __restrict__ out)
{
    const int gid = blockIdx.x * blockDim.x + threadIdx.x;   // over T*H/8
    const int t = gid >> 7, c8 = gid & 127;

    float4 a0 = ((const float4*)x)[gid*2];
    float4 a1 = ((const float4*)x)[gid*2+1];
    #pragma unroll
    for (int k = 0; k < TOPK; k++) {
        const uint4 yv = ((const uint4*)(g_yh + (size_t)(t * TOPK + k) * HDIM))[c8];
        const float2 p0 = __half22float2(*(const __half2*)&yv.x);
        const float2 p1 = __half22float2(*(const __half2*)&yv.y);
        const float2 p2 = __half22float2(*(const __half2*)&yv.z);
        const float2 p3 = __half22float2(*(const __half2*)&yv.w);
        a0.x += p0.x; a0.y += p0.y; a0.z += p1.x; a0.w += p1.y;
        a1.x += p2.x; a1.y += p2.y; a1.z += p3.x; a1.w += p3.y;
    }
    ((float4*)out)[gid*2]   = a0;
    ((float4*)out)[gid*2+1] = a1;

    if (gid < NEXP) g_cnt[gid] = 0;
}

extern "C" void kernel_launch(void* const* d_in, const int* in_sizes, int n_in,
                              void* d_out, int out_size)
{
    const float* x   = (const float*)d_in[0];
    const float* nw  = (const float*)d_in[1];
    const float* rw  = (const float*)d_in[2];
    const float* rb  = (const float*)d_in[3];
    const float* w13 = (const float*)d_in[4];
    const float* b13 = (const float*)d_in[5];
    const float* w2  = (const float*)d_in[6];
    const float* b2  = (const float*)d_in[7];
    const float* mw  = (const float*)d_in[8];
    const int*   li  = (n_in >= 10) ? (const int*)d_in[9] : nullptr;
    float* out = (float*)d_out;

    cudaFuncSetAttribute((const void*)k_mma<1>,
                         cudaFuncAttributeMaxDynamicSharedMemorySize, SMEM_MMA);
    cudaFuncSetAttribute((const void*)k_mma<0>,
                         cudaFuncAttributeMaxDynamicSharedMemorySize, SMEM_MMA);

    k_norm_router<<<T_TOK, 256>>>(x, nw, rw, rb, mw, li);
    k_mma<1><<<dim3(16, 8, NEXP), 256, SMEM_MMA>>>(w13, b13);
    k_mma<0><<<dim3(8, 8, NEXP), 256, SMEM_MMA>>>(w2, b2);
    k_combine<<<(T_TOK * HDIM / 8) / 256, 256>>>(x, out);
}